// round 16
// baseline (speedup 1.0000x reference)
#include <cuda_runtime.h>
#include <cuda_bf16.h>

// Problem constants: B=512, S=32768, alpha=0.1, beta=0.9
#define B_CONST 512
#define S_CONST 32768

// log2 constants (MUFU.LG2 domain). Whole sum scales by ln2, applied once
// in the final kernel. Note log2(1-alpha)=log2(beta), log2(1-beta)=log2(alpha).
#define L2_A   (-3.3219280948873623f)    // log2(0.1)
#define L2_1A  (-0.15200309344504997f)   // log2(0.9)
#define L2_B   (-0.15200309344504997f)   // log2(0.9)
#define L2_1B  (-3.3219280948873623f)    // log2(0.1)

constexpr int THREADS = 256;              // 8 warps
constexpr int ITERS   = 8;                // float4-iterations per warp
constexpr int WSEG    = ITERS * 64;       // 512 s-values per warp
constexpr int CHUNK   = (THREADS / 32) * WSEG;   // 4096 s per tile
constexpr int BPR     = S_CONST / CHUNK;  // 8 tiles per row
constexpr int NTILES  = B_CONST * BPR;    // 4096 tiles
constexpr int GRID_P  = 148 * 4;          // 592 persistent blocks
constexpr unsigned FULL = 0xffffffffu;

__device__ float        g_partials[GRID_P];
__device__ unsigned int g_next;           // work queue; final kernel resets

// KL transition term in log2 domain: prev=(pp0,pp1), curr=(q0,q1).
__device__ __forceinline__ float div_term_l(float pp0, float pp1,
                                            float q0, float q1,
                                            float l0, float l1)
{
    float t1 = q1 * (l1 - L2_B)  + q0 * (l0 - L2_1B);
    float t2 = q1 * (l1 - L2_1B) + q0 * (l0 - L2_B);
    return pp1 * t1 + pp0 * t2;
}

__global__ __launch_bounds__(THREADS)
void ekl_main_kernel(const float* __restrict__ post,
                     const int* __restrict__ length)
{
    const int lane = threadIdx.x & 31;
    const int warp = threadIdx.x >> 5;

    __shared__ unsigned s_tile;
    float sum = 0.0f;

    for (;;) {
        // One thread grabs the next tile; dynamic queue -> no waves, and
        // random-length imbalance self-levels across persistent blocks.
        if (threadIdx.x == 0)
            s_tile = atomicAdd(&g_next, 1u);
        __syncthreads();
        const unsigned t = s_tile;
        __syncthreads();               // s_tile consumed before next iter
        if (t >= (unsigned)NTILES) break;

        // Chunk-major: tiles [0,512) = chunk 0 (always full work) first;
        // high chunks (mostly masked, near-zero cost) drain at the end.
        const int c   = (int)(t >> 9);     // t / B_CONST
        const int b   = (int)(t & 511u);   // t % B_CONST
        const int len = length[b];         // 1 <= len <= S (int32, cached)
        const int s0  = c * CHUNK;

        const int segbase = s0 + warp * WSEG;
        if (segbase >= len) continue;      // warp-uniform skip

        const float2* row  = reinterpret_cast<const float2*>(post)
                             + (size_t)b * S_CONST;
        const float4* rowq = reinterpret_cast<const float4*>(row);
        const int qbase = (segbase >> 1) + lane;   // this lane's first quad

        // Cross-warp-boundary seed: pair at s = segbase-1 (lane 0 only).
        float sd0 = 0.0f, sd1 = 0.0f;
        if (segbase > 0 && lane == 0) {
            float2 pv = row[segbase - 1];
            sd0 = pv.x; sd1 = pv.y;
        }

        if (segbase > 0 && segbase + WSEG <= len) {
            // ---- FAST PATH (warp-uniform): every transition valid. ----
            float4 V[ITERS];
            #pragma unroll
            for (int i = 0; i < ITERS; ++i)
                V[i] = rowq[qbase + i * 32];

            #pragma unroll
            for (int i = 0; i < ITERS; ++i) {
                float c0a = V[i].x, c1a = V[i].y;   // pair at s
                float c0b = V[i].z, c1b = V[i].w;   // pair at s+1

                // prev for lane>0: neighbor's (z,w). lane 0: lane 31 of the
                // PREVIOUS quad (independent shuffle, no loop carry).
                float pv0 = __shfl_up_sync(FULL, c0b, 1);
                float pv1 = __shfl_up_sync(FULL, c1b, 1);
                float b0, b1;
                if (i == 0) { b0 = sd0; b1 = sd1; }
                else {
                    b0 = __shfl_sync(FULL, V[i-1].z, 31);
                    b1 = __shfl_sync(FULL, V[i-1].w, 31);
                }
                if (lane == 0) { pv0 = b0; pv1 = b1; }

                float l0a = __log2f(c0a), l1a = __log2f(c1a);
                float l0b = __log2f(c0b), l1b = __log2f(c1b);

                sum += div_term_l(pv0, pv1, c0a, c1a, l0a, l1a);
                sum += div_term_l(c0a, c1a, c0b, c1b, l0b, l1b);
            }
        } else {
            // ---- SLOW PATH: segment contains s==0 or the len cutoff. ----
            float4 V[ITERS];
            #pragma unroll
            for (int i = 0; i < ITERS; ++i)
                if (segbase + i * 64 < len)
                    V[i] = rowq[qbase + i * 32];

            float cr0 = sd0, cr1 = sd1;
            #pragma unroll
            for (int i = 0; i < ITERS; ++i) {
                if (segbase + i * 64 >= len) break;   // warp-uniform

                float c0a = V[i].x, c1a = V[i].y;
                float c0b = V[i].z, c1b = V[i].w;

                float pv0 = __shfl_up_sync(FULL, c0b, 1);
                float pv1 = __shfl_up_sync(FULL, c1b, 1);
                if (lane == 0) { pv0 = cr0; pv1 = cr1; }

                const int sidx = segbase + i * 64 + 2 * lane;

                float l0a = __log2f(c0a), l1a = __log2f(c1a);
                float l0b = __log2f(c0b), l1b = __log2f(c1b);

                if (sidx == 0) {
                    // first-term contribution at s = 0 (len >= 1 always)
                    sum += c1a * (l1a - L2_A) + c0a * (l0a - L2_1A);
                } else if (sidx < len) {
                    sum += div_term_l(pv0, pv1, c0a, c1a, l0a, l1a);
                }
                if (sidx + 1 < len)
                    sum += div_term_l(c0a, c1a, c0b, c1b, l0b, l1b);

                cr0 = __shfl_sync(FULL, c0b, 31);
                cr1 = __shfl_sync(FULL, c1b, 31);
            }
        }
    }

    // Deterministic-order block reduction: warp shuffle tree + smem
    #pragma unroll
    for (int off = 16; off > 0; off >>= 1)
        sum += __shfl_down_sync(FULL, sum, off);

    __shared__ float wsum[THREADS / 32];
    if (lane == 0) wsum[warp] = sum;
    __syncthreads();

    if (warp == 0) {
        float v = (lane < THREADS / 32) ? wsum[lane] : 0.0f;
        #pragma unroll
        for (int off = 4; off > 0; off >>= 1)
            v += __shfl_down_sync(FULL, v, off);
        if (lane == 0) g_partials[blockIdx.x] = v;
    }
}

// Final reduction: 592 partials, one scalar load each; fixed order.
// Also applies the ln2 scale (log2 -> ln) and the 1/B mean, and resets
// the work queue for the next graph replay.
__global__ __launch_bounds__(1024)
void ekl_final_kernel(float* __restrict__ out)
{
    float s = (threadIdx.x < GRID_P) ? g_partials[threadIdx.x] : 0.0f;

    #pragma unroll
    for (int off = 16; off > 0; off >>= 1)
        s += __shfl_down_sync(0xffffffffu, s, off);

    __shared__ float wsum[32];
    const int lane = threadIdx.x & 31;
    const int wid  = threadIdx.x >> 5;
    if (lane == 0) wsum[wid] = s;
    __syncthreads();

    if (wid == 0) {
        float v = wsum[lane];   // 32 warps exactly
        #pragma unroll
        for (int off = 16; off > 0; off >>= 1)
            v += __shfl_down_sync(0xffffffffu, v, off);
        if (lane == 0) {
            out[0] = v * (0.6931471805599453f / (float)B_CONST);  // ln2 / B
            g_next = 0;                  // reset queue for next replay
        }
    }
}

extern "C" void kernel_launch(void* const* d_in, const int* in_sizes, int n_in,
                              void* d_out, int out_size)
{
    const float* post = (const float*)d_in[0];   // (B, S, 2) f32 interleaved
    const int*   len  = (const int*)d_in[1];     // (B,) int32 on device
    float*       out  = (float*)d_out;           // scalar f32

    ekl_main_kernel<<<GRID_P, THREADS>>>(post, len);
    ekl_final_kernel<<<1, 1024>>>(out);
}

// round 17
// speedup vs baseline: 1.1352x; 1.1352x over previous
#include <cuda_runtime.h>
#include <cuda_bf16.h>

// Problem constants: B=512, S=32768, alpha=0.1, beta=0.9
#define B_CONST 512
#define S_CONST 32768

// log(0.1), log(0.9). Note log(1-alpha)=log(beta), log(1-beta)=log(alpha).
#define LOG_A   (-2.3025850929940457f)   // log(0.1)
#define LOG_1A  (-0.10536051565782628f)  // log(0.9)
#define LOG_B   (-0.10536051565782628f)  // log(0.9)
#define LOG_1B  (-2.3025850929940457f)   // log(0.1)

constexpr int THREADS = 256;              // 8 warps
constexpr int ITERS   = 8;                // float4-iterations per warp
constexpr int WSEG    = ITERS * 64;       // 512 s-values per warp
constexpr int CHUNK   = (THREADS / 32) * WSEG;   // 4096 s per block
constexpr int BPR     = S_CONST / CHUNK;  // 8 blocks per row
constexpr int GRID    = B_CONST * BPR;    // 4096 blocks
constexpr unsigned FULL = 0xffffffffu;

__device__ float g_acc;                   // zero-init; final kernel resets

// KL transition term: prev=(pp0,pp1), curr=(q0,q1); logs precomputed.
__device__ __forceinline__ float div_term_l(float pp0, float pp1,
                                            float q0, float q1,
                                            float l0, float l1)
{
    float t1 = q1 * (l1 - LOG_B)  + q0 * (l0 - LOG_1B);
    float t2 = q1 * (l1 - LOG_1B) + q0 * (l0 - LOG_B);
    return pp1 * t1 + pp0 * t2;
}

__global__ __launch_bounds__(THREADS)
void ekl_main_kernel(const float* __restrict__ post,
                     const int* __restrict__ length)
{
    const int bid  = blockIdx.x;
    const int b    = bid / BPR;
    const int c    = bid % BPR;
    const int len  = length[b];       // 1 <= len <= S (int32)
    const int s0   = c * CHUNK;
    const int lane = threadIdx.x & 31;
    const int warp = threadIdx.x >> 5;

    float sum = 0.0f;

    // Warp-uniform segment: s in [segbase, segbase + WSEG)
    const int segbase = s0 + warp * WSEG;

    if (segbase < len) {
        const float2* row  = reinterpret_cast<const float2*>(post)
                             + (size_t)b * S_CONST;
        const float4* rowq = reinterpret_cast<const float4*>(row);
        const int qbase = (segbase >> 1) + lane;   // this lane's first quad

        // Cross-warp-boundary carry: pair at s = segbase-1 (lane 0 only).
        float cr0 = 0.0f, cr1 = 0.0f;
        if (segbase > 0 && lane == 0) {
            float2 pv = row[segbase - 1];
            cr0 = pv.x; cr1 = pv.y;
        }

        if (segbase > 0 && segbase + WSEG <= len) {
            // ---- FAST PATH (warp-uniform): every transition valid. ----
            float4 V[ITERS];
            #pragma unroll
            for (int i = 0; i < ITERS; ++i)
                V[i] = rowq[qbase + i * 32];

            #pragma unroll
            for (int i = 0; i < ITERS; ++i) {
                float c0a = V[i].x, c1a = V[i].y;   // pair at s
                float c0b = V[i].z, c1b = V[i].w;   // pair at s+1

                float pv0 = __shfl_up_sync(FULL, c0b, 1);
                float pv1 = __shfl_up_sync(FULL, c1b, 1);
                if (lane == 0) { pv0 = cr0; pv1 = cr1; }

                float l0a = __logf(c0a), l1a = __logf(c1a);
                float l0b = __logf(c0b), l1b = __logf(c1b);

                sum += div_term_l(pv0, pv1, c0a, c1a, l0a, l1a);
                sum += div_term_l(c0a, c1a, c0b, c1b, l0b, l1b);

                cr0 = __shfl_sync(FULL, c0b, 31);
                cr1 = __shfl_sync(FULL, c1b, 31);
            }
        } else {
            // ---- SLOW PATH: segment contains s==0 or the len cutoff. ----
            float4 V[ITERS];
            #pragma unroll
            for (int i = 0; i < ITERS; ++i)
                if (segbase + i * 64 < len)
                    V[i] = rowq[qbase + i * 32];

            #pragma unroll
            for (int i = 0; i < ITERS; ++i) {
                if (segbase + i * 64 >= len) break;   // warp-uniform

                float c0a = V[i].x, c1a = V[i].y;
                float c0b = V[i].z, c1b = V[i].w;

                float pv0 = __shfl_up_sync(FULL, c0b, 1);
                float pv1 = __shfl_up_sync(FULL, c1b, 1);
                if (lane == 0) { pv0 = cr0; pv1 = cr1; }

                const int sidx = segbase + i * 64 + 2 * lane;

                float l0a = __logf(c0a), l1a = __logf(c1a);
                float l0b = __logf(c0b), l1b = __logf(c1b);

                if (sidx == 0) {
                    // first-term contribution at s = 0 (len >= 1 always)
                    sum += c1a * (l1a - LOG_A) + c0a * (l0a - LOG_1A);
                } else if (sidx < len) {
                    sum += div_term_l(pv0, pv1, c0a, c1a, l0a, l1a);
                }
                if (sidx + 1 < len)
                    sum += div_term_l(c0a, c1a, c0b, c1b, l0b, l1b);

                cr0 = __shfl_sync(FULL, c0b, 31);
                cr1 = __shfl_sync(FULL, c1b, 31);
            }
        }
    }

    // Deterministic block reduction: warp shuffle tree + smem
    #pragma unroll
    for (int off = 16; off > 0; off >>= 1)
        sum += __shfl_down_sync(FULL, sum, off);

    __shared__ float wsum[THREADS / 32];
    if (lane == 0) wsum[warp] = sum;
    __syncthreads();

    if (warp == 0) {
        float v = (lane < THREADS / 32) ? wsum[lane] : 0.0f;
        #pragma unroll
        for (int off = 4; off > 0; off >>= 1)
            v += __shfl_down_sync(FULL, v, off);
        if (lane == 0) {
            // Fire-and-forget reduction at L2: non-returning RED, no wait,
            // no fence (the kernel-boundary edge orders it before the
            // final kernel's read). NOT the convicted returning-atomic path.
            asm volatile("red.global.add.f32 [%0], %1;"
                         :: "l"(&g_acc), "f"(v) : "memory");
        }
    }
}

// Minimal final kernel: one scalar read + scale + write + queue reset.
__global__ void ekl_final_kernel(float* __restrict__ out)
{
    if (threadIdx.x == 0) {
        out[0] = g_acc * (1.0f / (float)B_CONST);
        g_acc  = 0.0f;                // reset for next graph replay
    }
}

extern "C" void kernel_launch(void* const* d_in, const int* in_sizes, int n_in,
                              void* d_out, int out_size)
{
    const float* post = (const float*)d_in[0];   // (B, S, 2) f32 interleaved
    const int*   len  = (const int*)d_in[1];     // (B,) int32 on device
    float*       out  = (float*)d_out;           // scalar f32

    ekl_main_kernel<<<GRID, THREADS>>>(post, len);
    ekl_final_kernel<<<1, 32>>>(out);
}